// round 4
// baseline (speedup 1.0000x reference)
#include <cuda_runtime.h>
#include <cstdint>

// Problem constants
#define B_     8
#define CDIM   64
#define NPOS   9216      // 96*96
#define INNER  128
#define O3     384       // 3*INNER
#define HEADS  4
#define DHEAD  32
#define NCH    9
#define CHUNK  1024
#define NGC    (32 * NCH)   // 288 (g, ch) pairs
#define GN_TILES 72
#define K4_TILES 36

// Scratch (device globals — no allocations allowed)
__device__ __align__(16) float g_qkv[(size_t)B_ * O3 * NPOS];      // [b][o][n]
__device__ float g_part[B_][8][GN_TILES][2];                        // groupnorm partials
__device__ float g_stats[NGC][DHEAD][2];                            // q row {max, 1/sum}
__device__ __align__(16) float g_Apart[NGC][8][DHEAD * DHEAD];      // partial A
__device__ __align__(16) float g_Weff[B_ * NCH][2][CDIM][INNER];    // fused weights hi/lo

// ---------------------------------------------------------------------------
__device__ __forceinline__ uint32_t f2tf(float x) {
    uint32_t r;
    asm("cvt.rna.tf32.f32 %0, %1;" : "=r"(r) : "f"(x));
    return r;
}

#define MMA(d, a, b)                                                          \
    asm volatile(                                                             \
        "mma.sync.aligned.m16n8k8.row.col.f32.tf32.tf32.f32 "                 \
        "{%0,%1,%2,%3},{%4,%5,%6,%7},{%8,%9},{%0,%1,%2,%3};"                  \
        : "+f"((d)[0]), "+f"((d)[1]), "+f"((d)[2]), "+f"((d)[3])              \
        : "r"((a)[0]), "r"((a)[1]), "r"((a)[2]), "r"((a)[3]),                 \
          "r"((b)[0]), "r"((b)[1]))

// ---------------------------------------------------------------------------
// K1 (mma): qkv[b][o][n] = sum_c W_qkv[o][c] * x[b][c][n]   (unchanged)
// ---------------------------------------------------------------------------
#define K1_APAD 68
#define K1_BPAD 132
#define K1_SMEM ((128 * K1_APAD * 2 + 64 * K1_BPAD * 2) * 4)

__global__ __launch_bounds__(256, 1) void qkv_mma_kernel(const float* __restrict__ x,
                                                         const float* __restrict__ Wq) {
    extern __shared__ uint32_t smu[];
    uint32_t* Ahi = smu;
    uint32_t* Alo = Ahi + 128 * K1_APAD;
    uint32_t* Bhi = Alo + 128 * K1_APAD;
    uint32_t* Blo = Bhi + 64 * K1_BPAD;

    const int b = blockIdx.z, mt = blockIdx.y, n0 = blockIdx.x * 128;
    const int tid = threadIdx.x;

    for (int idx = tid; idx < 128 * 16; idx += 256) {
        int row = idx >> 4, c4 = (idx & 15) * 4;
        float4 w = *(const float4*)(Wq + (size_t)(mt * 128 + row) * CDIM + c4);
        float v[4] = {w.x, w.y, w.z, w.w};
#pragma unroll
        for (int j = 0; j < 4; j++) {
            uint32_t h = f2tf(v[j]);
            Ahi[row * K1_APAD + c4 + j] = h;
            Alo[row * K1_APAD + c4 + j] = f2tf(v[j] - __uint_as_float(h));
        }
    }
    for (int idx = tid; idx < 64 * 32; idx += 256) {
        int c = idx >> 5, n4 = (idx & 31) * 4;
        float4 w = *(const float4*)(x + (size_t)b * CDIM * NPOS + (size_t)c * NPOS + n0 + n4);
        float v[4] = {w.x, w.y, w.z, w.w};
#pragma unroll
        for (int j = 0; j < 4; j++) {
            uint32_t h = f2tf(v[j]);
            Bhi[c * K1_BPAD + n4 + j] = h;
            Blo[c * K1_BPAD + n4 + j] = f2tf(v[j] - __uint_as_float(h));
        }
    }
    __syncthreads();

    const int wid = tid >> 5, lane = tid & 31, g = lane >> 2, tig = lane & 3;
    const int wm = (wid >> 2) * 64, wn = (wid & 3) * 32;

    float c[4][4][4];
#pragma unroll
    for (int i = 0; i < 4; i++)
#pragma unroll
        for (int j = 0; j < 4; j++)
#pragma unroll
            for (int q = 0; q < 4; q++) c[i][j][q] = 0.f;

#pragma unroll
    for (int k8 = 0; k8 < 8; k8++) {
        const int kb = k8 * 8;
        uint32_t ah[4][4], al[4][4];
#pragma unroll
        for (int mf = 0; mf < 4; mf++) {
            int r0 = (wm + mf * 16 + g) * K1_APAD + kb + tig;
            int r1 = r0 + 8 * K1_APAD;
            ah[mf][0] = Ahi[r0]; ah[mf][1] = Ahi[r1];
            ah[mf][2] = Ahi[r0 + 4]; ah[mf][3] = Ahi[r1 + 4];
            al[mf][0] = Alo[r0]; al[mf][1] = Alo[r1];
            al[mf][2] = Alo[r0 + 4]; al[mf][3] = Alo[r1 + 4];
        }
        uint32_t bh[4][2], bl[4][2];
#pragma unroll
        for (int nf = 0; nf < 4; nf++) {
            int c0 = (kb + tig) * K1_BPAD + wn + nf * 8 + g;
            bh[nf][0] = Bhi[c0]; bh[nf][1] = Bhi[c0 + 4 * K1_BPAD];
            bl[nf][0] = Blo[c0]; bl[nf][1] = Blo[c0 + 4 * K1_BPAD];
        }
#pragma unroll
        for (int mf = 0; mf < 4; mf++)
#pragma unroll
            for (int nf = 0; nf < 4; nf++) {
                MMA(c[mf][nf], ah[mf], bh[nf]);
                MMA(c[mf][nf], ah[mf], bl[nf]);
                MMA(c[mf][nf], al[mf], bh[nf]);
            }
    }

    float* op = g_qkv + ((size_t)b * O3 + mt * 128 + wm) * NPOS + n0 + wn;
#pragma unroll
    for (int mf = 0; mf < 4; mf++)
#pragma unroll
        for (int nf = 0; nf < 4; nf++) {
            int col = nf * 8 + tig * 2;
            *(float2*)(op + (size_t)(mf * 16 + g) * NPOS + col) =
                make_float2(c[mf][nf][0], c[mf][nf][1]);
            *(float2*)(op + (size_t)(mf * 16 + g + 8) * NPOS + col) =
                make_float2(c[mf][nf][2], c[mf][nf][3]);
        }
}

// ---------------------------------------------------------------------------
// ATT1: q row softmax stats. grid (9, 32), 256 threads.  (unchanged)
// ---------------------------------------------------------------------------
__global__ __launch_bounds__(256, 4) void att_stats_kernel() {
    const int ch = blockIdx.x, g = blockIdx.y, gc = g * NCH + ch;
    const int b = g >> 2, head = g & 3;
    const int tid = threadIdx.x, lane = tid & 31, wrp = tid >> 5;

    const float* qbase = g_qkv + ((size_t)(b * O3 + head * DHEAD)) * NPOS + ch * CHUNK;
#pragma unroll
    for (int r = 0; r < 4; r++) {
        int d = wrp * 4 + r;
        const float* row = qbase + (size_t)d * NPOS;
        float m = -1e30f;
        for (int c = lane; c < CHUNK; c += 32) m = fmaxf(m, row[c]);
        for (int off = 16; off; off >>= 1) m = fmaxf(m, __shfl_xor_sync(0xffffffffu, m, off));
        float s = 0.f;
        for (int c = lane; c < CHUNK; c += 32) s += __expf(row[c] - m);
        for (int off = 16; off; off >>= 1) s += __shfl_xor_sync(0xffffffffu, s, off);
        if (lane == 0) {
            g_stats[gc][d][0] = m;
            g_stats[gc][d][1] = 1.0f / s;
        }
    }
}

// ---------------------------------------------------------------------------
// ATT2: partial A over 128 positions. grid (9, 32, 8), 128 threads. (unchanged)
// ---------------------------------------------------------------------------
#define A2_PAD 132
#define A2_ARR (DHEAD * A2_PAD)
#define A2_SMEM (4 * A2_ARR * 4 + 128)

__global__ __launch_bounds__(128, 3) void att_a_kernel() {
    extern __shared__ uint32_t sm2[];
    uint32_t* Eqh = sm2;
    uint32_t* Eql = Eqh + A2_ARR;
    uint32_t* Ksh = Eql + A2_ARR;
    uint32_t* Ksl = Ksh + A2_ARR;
    float* sm_m = (float*)(Ksl + A2_ARR);
    float* Apart = (float*)sm2;

    const int ch = blockIdx.x, g = blockIdx.y, sub = blockIdx.z;
    const int gc = g * NCH + ch;
    const int b = g >> 2, head = g & 3;
    const int tid = threadIdx.x, lane = tid & 31, wrp = tid >> 5;
    const int j = tid;

    const float* qbase = g_qkv + ((size_t)(b * O3 + head * DHEAD)) * NPOS + ch * CHUNK + sub * 128;
    const float* kbase = qbase + (size_t)INNER * NPOS;

    if (tid < DHEAD) sm_m[tid] = g_stats[gc][tid][0];

    float kr[DHEAD];
#pragma unroll
    for (int d = 0; d < DHEAD; d++) kr[d] = kbase[(size_t)d * NPOS + j];
    float km = -1e30f;
#pragma unroll
    for (int d = 0; d < DHEAD; d++) km = fmaxf(km, kr[d]);
    float ks = 0.f;
#pragma unroll
    for (int d = 0; d < DHEAD; d++) { kr[d] = __expf(kr[d] - km); ks += kr[d]; }
    float kinv = 1.0f / ks;
#pragma unroll
    for (int d = 0; d < DHEAD; d++) {
        float v = kr[d] * kinv;
        uint32_t h = f2tf(v);
        Ksh[d * A2_PAD + j] = h;
        Ksl[d * A2_PAD + j] = f2tf(v - __uint_as_float(h));
    }

    float qr[DHEAD];
#pragma unroll
    for (int d = 0; d < DHEAD; d++) qr[d] = qbase[(size_t)d * NPOS + j];
    __syncthreads();
#pragma unroll
    for (int d = 0; d < DHEAD; d++) {
        float v = __expf(qr[d] - sm_m[d]);
        uint32_t h = f2tf(v);
        Eqh[d * A2_PAD + j] = h;
        Eql[d * A2_PAD + j] = f2tf(v - __uint_as_float(h));
    }
    __syncthreads();

    const int gq = lane >> 2, tig = lane & 3;
    float acc[2][4][4];
#pragma unroll
    for (int i = 0; i < 2; i++)
#pragma unroll
        for (int jj = 0; jj < 4; jj++)
#pragma unroll
            for (int q = 0; q < 4; q++) acc[i][jj][q] = 0.f;

#pragma unroll
    for (int kk = 0; kk < 4; kk++) {
        const int kb = (wrp * 4 + kk) * 8;
        uint32_t ah[2][4], al[2][4];
#pragma unroll
        for (int mf = 0; mf < 2; mf++) {
            int r0 = (mf * 16 + gq) * A2_PAD + kb + tig;
            int r1 = r0 + 8 * A2_PAD;
            ah[mf][0] = Eqh[r0]; ah[mf][1] = Eqh[r1];
            ah[mf][2] = Eqh[r0 + 4]; ah[mf][3] = Eqh[r1 + 4];
            al[mf][0] = Eql[r0]; al[mf][1] = Eql[r1];
            al[mf][2] = Eql[r0 + 4]; al[mf][3] = Eql[r1 + 4];
        }
        uint32_t bh[4][2], bl[4][2];
#pragma unroll
        for (int nf = 0; nf < 4; nf++) {
            int c0 = (nf * 8 + gq) * A2_PAD + kb + tig;
            bh[nf][0] = Ksh[c0]; bh[nf][1] = Ksh[c0 + 4];
            bl[nf][0] = Ksl[c0]; bl[nf][1] = Ksl[c0 + 4];
        }
#pragma unroll
        for (int mf = 0; mf < 2; mf++)
#pragma unroll
            for (int nf = 0; nf < 4; nf++) {
                MMA(acc[mf][nf], ah[mf], bh[nf]);
                MMA(acc[mf][nf], ah[mf], bl[nf]);
                MMA(acc[mf][nf], al[mf], bh[nf]);
            }
    }
    __syncthreads();

#pragma unroll
    for (int mf = 0; mf < 2; mf++)
#pragma unroll
        for (int nf = 0; nf < 4; nf++) {
            int row = mf * 16 + gq, col = nf * 8 + tig * 2;
            Apart[(wrp * 32 + row) * 33 + col]     = acc[mf][nf][0];
            Apart[(wrp * 32 + row) * 33 + col + 1] = acc[mf][nf][1];
            Apart[(wrp * 32 + row + 8) * 33 + col]     = acc[mf][nf][2];
            Apart[(wrp * 32 + row + 8) * 33 + col + 1] = acc[mf][nf][3];
        }
    __syncthreads();

    float* out = g_Apart[gc][sub];
#pragma unroll
    for (int r = 0; r < 8; r++) {
        int idx = tid + 128 * r;
        int d = idx >> 5, dp = idx & 31;
        float s = 0.f;
#pragma unroll
        for (int w = 0; w < 4; w++) s += Apart[(w * 32 + d) * 33 + dp];
        out[idx] = s;
    }
}

// ---------------------------------------------------------------------------
// WEFF: W_eff[b,ch] = W_out @ blockdiag(A_heads), output split hi/lo.
// grid (9, 8), 256 threads.
// ---------------------------------------------------------------------------
__global__ __launch_bounds__(256, 4) void weff_kernel(const float* __restrict__ Wout) {
    __shared__ float A_s[HEADS][DHEAD][DHEAD + 1];
    const int ch = blockIdx.x, b = blockIdx.y, cc = b * NCH + ch;
    const int tid = threadIdx.x;

    // reduce A partials + apply 1/Zq
    for (int idx = tid; idx < HEADS * DHEAD * DHEAD; idx += 256) {
        int head = idx >> 10, e = idx & 1023, d = e >> 5, dp = e & 31;
        int gc = (b * HEADS + head) * NCH + ch;
        const float* ap = g_Apart[gc][0] + e;
        float s = 0.f;
#pragma unroll
        for (int sub = 0; sub < 8; sub++) s += ap[sub * DHEAD * DHEAD];
        A_s[head][d][dp] = s * g_stats[gc][d][1];
    }
    __syncthreads();

    // W_eff[o][head*32+dp] = sum_d W_out[o][head*32+d] * A_s[head][d][dp]
#pragma unroll
    for (int r = 0; r < 32; r++) {
        int idx = tid + 256 * r;
        int o = idx >> 7, ic = idx & 127, head = ic >> 5, dp = ic & 31;
        const float* wr = Wout + (size_t)o * INNER + head * DHEAD;
        float acc = 0.f;
#pragma unroll
        for (int d = 0; d < DHEAD; d++) acc += wr[d] * A_s[head][d][dp];
        uint32_t h = f2tf(acc);
        g_Weff[cc][0][o][ic] = __uint_as_float(h);
        g_Weff[cc][1][o][ic] = __uint_as_float(f2tf(acc - __uint_as_float(h)));
    }
}

// ---------------------------------------------------------------------------
// K3' (fused): y = W_eff(b,ch) @ V + b_out, with groupnorm partials.
// CTA tile [64 M x 128 N], K=128. grid (72, 8), 256 threads.
// ---------------------------------------------------------------------------
#define K3_PAD 132
#define K3_SMEM ((64 * K3_PAD * 2 + 128 * K3_PAD * 2) * 4)

__global__ __launch_bounds__(256, 1) void outproj_mma_kernel(const float* __restrict__ bout,
                                                             float* __restrict__ y) {
    extern __shared__ uint32_t smu[];
    uint32_t* Ahi = smu;
    uint32_t* Alo = Ahi + 64 * K3_PAD;
    uint32_t* Bhi = Alo + 64 * K3_PAD;
    uint32_t* Blo = Bhi + 128 * K3_PAD;
    __shared__ float swp[8][8][2];

    const int b = blockIdx.y, n0 = blockIdx.x * 128, tid = threadIdx.x;
    const int cc = b * NCH + (n0 / CHUNK);

    // A tile: pre-split W_eff (straight copy, no conversion)
    for (int idx = tid; idx < 64 * 32; idx += 256) {
        int row = idx >> 5, c4 = (idx & 31) * 4;
        float4 h = *(const float4*)(&g_Weff[cc][0][row][c4]);
        float4 l = *(const float4*)(&g_Weff[cc][1][row][c4]);
        Ahi[row * K3_PAD + c4]     = __float_as_uint(h.x);
        Ahi[row * K3_PAD + c4 + 1] = __float_as_uint(h.y);
        Ahi[row * K3_PAD + c4 + 2] = __float_as_uint(h.z);
        Ahi[row * K3_PAD + c4 + 3] = __float_as_uint(h.w);
        Alo[row * K3_PAD + c4]     = __float_as_uint(l.x);
        Alo[row * K3_PAD + c4 + 1] = __float_as_uint(l.y);
        Alo[row * K3_PAD + c4 + 2] = __float_as_uint(l.z);
        Alo[row * K3_PAD + c4 + 3] = __float_as_uint(l.w);
    }
    // B tile: V channels [128 K x 128 N] from g_qkv, split to tf32 hi/lo
    const float* vbase = g_qkv + ((size_t)b * O3 + 2 * INNER) * NPOS + n0;
    for (int idx = tid; idx < 128 * 32; idx += 256) {
        int ic = idx >> 5, n4 = (idx & 31) * 4;
        float4 w = *(const float4*)(vbase + (size_t)ic * NPOS + n4);
        float v[4] = {w.x, w.y, w.z, w.w};
#pragma unroll
        for (int j = 0; j < 4; j++) {
            uint32_t h = f2tf(v[j]);
            Bhi[ic * K3_PAD + n4 + j] = h;
            Blo[ic * K3_PAD + n4 + j] = f2tf(v[j] - __uint_as_float(h));
        }
    }
    __syncthreads();

    const int wid = tid >> 5, lane = tid & 31, g = lane >> 2, tig = lane & 3;
    const int wn = wid * 16;

    float acc[4][2][4];
#pragma unroll
    for (int i = 0; i < 4; i++)
#pragma unroll
        for (int j = 0; j < 2; j++)
#pragma unroll
            for (int q = 0; q < 4; q++) acc[i][j][q] = 0.f;

#pragma unroll
    for (int k8 = 0; k8 < 16; k8++) {
        const int kb = k8 * 8;
        uint32_t ah[4][4], al[4][4];
#pragma unroll
        for (int mf = 0; mf < 4; mf++) {
            int r0 = (mf * 16 + g) * K3_PAD + kb + tig;
            int r1 = r0 + 8 * K3_PAD;
            ah[mf][0] = Ahi[r0]; ah[mf][1] = Ahi[r1];
            ah[mf][2] = Ahi[r0 + 4]; ah[mf][3] = Ahi[r1 + 4];
            al[mf][0] = Alo[r0]; al[mf][1] = Alo[r1];
            al[mf][2] = Alo[r0 + 4]; al[mf][3] = Alo[r1 + 4];
        }
        uint32_t bh[2][2], bl[2][2];
#pragma unroll
        for (int nf = 0; nf < 2; nf++) {
            int c0 = (kb + tig) * K3_PAD + wn + nf * 8 + g;
            bh[nf][0] = Bhi[c0]; bh[nf][1] = Bhi[c0 + 4 * K3_PAD];
            bl[nf][0] = Blo[c0]; bl[nf][1] = Blo[c0 + 4 * K3_PAD];
        }
#pragma unroll
        for (int mf = 0; mf < 4; mf++)
#pragma unroll
            for (int nf = 0; nf < 2; nf++) {
                MMA(acc[mf][nf], ah[mf], bh[nf]);
                MMA(acc[mf][nf], ah[mf], bl[nf]);
                MMA(acc[mf][nf], al[mf], bh[nf]);
            }
    }

    float gs[8], gq[8];
#pragma unroll
    for (int i = 0; i < 8; i++) { gs[i] = 0.f; gq[i] = 0.f; }

    float* yp = y + (size_t)b * CDIM * NPOS + n0 + wn;
#pragma unroll
    for (int mf = 0; mf < 4; mf++) {
        float bias0 = __ldg(bout + mf * 16 + g);
        float bias1 = __ldg(bout + mf * 16 + g + 8);
#pragma unroll
        for (int nf = 0; nf < 2; nf++) {
            int col = nf * 8 + tig * 2;
            float v0 = acc[mf][nf][0] + bias0, v1 = acc[mf][nf][1] + bias0;
            float v2 = acc[mf][nf][2] + bias1, v3 = acc[mf][nf][3] + bias1;
            *(float2*)(yp + (size_t)(mf * 16 + g) * NPOS + col) = make_float2(v0, v1);
            *(float2*)(yp + (size_t)(mf * 16 + g + 8) * NPOS + col) = make_float2(v2, v3);
            gs[2 * mf]     += v0 + v1;
            gq[2 * mf]     += v0 * v0 + v1 * v1;
            gs[2 * mf + 1] += v2 + v3;
            gq[2 * mf + 1] += v2 * v2 + v3 * v3;
        }
    }

#pragma unroll
    for (int gr = 0; gr < 8; gr++) {
        float s = gs[gr], q = gq[gr];
        for (int off = 16; off; off >>= 1) {
            s += __shfl_xor_sync(0xffffffffu, s, off);
            q += __shfl_xor_sync(0xffffffffu, q, off);
        }
        if (lane == 0) { swp[wid][gr][0] = s; swp[wid][gr][1] = q; }
    }
    __syncthreads();
    if (tid < 16) {
        int gr = tid >> 1, qq = tid & 1;
        float s = 0.f;
#pragma unroll
        for (int w = 0; w < 8; w++) s += swp[w][gr][qq];
        g_part[b][gr][blockIdx.x][qq] = s;
    }
}

// ---------------------------------------------------------------------------
// K4: groupnorm finalize (unchanged)
// ---------------------------------------------------------------------------
__global__ void gnorm_kernel(float* __restrict__ y,
                             const float* __restrict__ gamma,
                             const float* __restrict__ beta) {
    __shared__ float tmp[8][2];
    __shared__ float mu[8], rs[8];
    const int b = blockIdx.y, n0 = blockIdx.x * 256, tid = threadIdx.x;

    if (tid < 16) {
        int g = tid >> 1, qq = tid & 1;
        float s = 0.f;
        for (int t = 0; t < GN_TILES; t++) s += g_part[b][g][t][qq];
        tmp[g][qq] = s;
    }
    __syncthreads();
    if (tid < 8) {
        const float invn = 1.0f / (8.0f * NPOS);
        float m = tmp[tid][0] * invn;
        float v = tmp[tid][1] * invn - m * m;
        mu[tid] = m;
        rs[tid] = rsqrtf(v + 1e-5f);
    }
    __syncthreads();

    float* yb = y + (size_t)b * CDIM * NPOS + n0 + tid;
    for (int c = 0; c < CDIM; c++) {
        float val = yb[(size_t)c * NPOS];
        int g = c >> 3;
        yb[(size_t)c * NPOS] = (val - mu[g]) * rs[g] * __ldg(gamma + c) + __ldg(beta + c);
    }
}

// ---------------------------------------------------------------------------
extern "C" void kernel_launch(void* const* d_in, const int* in_sizes, int n_in,
                              void* d_out, int out_size) {
    const float* x     = (const float*)d_in[0];
    const float* Wqkv  = (const float*)d_in[1];
    const float* Wout  = (const float*)d_in[2];
    const float* bout  = (const float*)d_in[3];
    const float* gamma = (const float*)d_in[4];
    const float* beta  = (const float*)d_in[5];
    float* y = (float*)d_out;

    cudaFuncSetAttribute(qkv_mma_kernel, cudaFuncAttributeMaxDynamicSharedMemorySize, K1_SMEM);
    cudaFuncSetAttribute(att_a_kernel, cudaFuncAttributeMaxDynamicSharedMemorySize, A2_SMEM);
    cudaFuncSetAttribute(outproj_mma_kernel, cudaFuncAttributeMaxDynamicSharedMemorySize, K3_SMEM);

    qkv_mma_kernel<<<dim3(72, 3, B_), 256, K1_SMEM>>>(x, Wqkv);
    att_stats_kernel<<<dim3(NCH, 32), 256>>>();
    att_a_kernel<<<dim3(NCH, 32, 8), 128, A2_SMEM>>>();
    weff_kernel<<<dim3(NCH, B_), 256>>>(Wout);
    outproj_mma_kernel<<<dim3(GN_TILES, B_), 256, K3_SMEM>>>(bout, y);
    gnorm_kernel<<<dim3(K4_TILES, B_), 256>>>(y, gamma, beta);
}

// round 5
// speedup vs baseline: 1.1173x; 1.1173x over previous
#include <cuda_runtime.h>
#include <cstdint>

// Problem constants
#define B_     8
#define CDIM   64
#define NPOS   9216      // 96*96
#define INNER  128
#define O3     384       // 3*INNER
#define HEADS  4
#define DHEAD  32
#define NCH    9
#define CHUNK  1024
#define NGC    (32 * NCH)   // 288 (g, ch) pairs
#define GN_TILES 72
#define K4_TILES 36

// Scratch (device globals — no allocations allowed)
__device__ __align__(16) float g_qkv[(size_t)B_ * O3 * NPOS];      // [b][o][n]
__device__ float g_part[B_][8][GN_TILES][2];                        // groupnorm partials
__device__ __align__(16) float g_Apart[NGC][8][DHEAD * DHEAD];      // partial A (unnormalized)
__device__ __align__(16) float g_Weff[B_ * NCH][2][CDIM][INNER];    // fused weights hi/lo

// ---------------------------------------------------------------------------
__device__ __forceinline__ uint32_t f2tf(float x) {
    uint32_t r;
    asm("cvt.rna.tf32.f32 %0, %1;" : "=r"(r) : "f"(x));
    return r;
}

#define MMA(d, a, b)                                                          \
    asm volatile(                                                             \
        "mma.sync.aligned.m16n8k8.row.col.f32.tf32.tf32.f32 "                 \
        "{%0,%1,%2,%3},{%4,%5,%6,%7},{%8,%9},{%0,%1,%2,%3};"                  \
        : "+f"((d)[0]), "+f"((d)[1]), "+f"((d)[2]), "+f"((d)[3])              \
        : "r"((a)[0]), "r"((a)[1]), "r"((a)[2]), "r"((a)[3]),                 \
          "r"((b)[0]), "r"((b)[1]))

// ---------------------------------------------------------------------------
// K1 (mma): qkv[b][o][n] = sum_c W_qkv[o][c] * x[b][c][n]   (unchanged)
// ---------------------------------------------------------------------------
#define K1_APAD 68
#define K1_BPAD 132
#define K1_SMEM ((128 * K1_APAD * 2 + 64 * K1_BPAD * 2) * 4)

__global__ __launch_bounds__(256, 1) void qkv_mma_kernel(const float* __restrict__ x,
                                                         const float* __restrict__ Wq) {
    extern __shared__ uint32_t smu[];
    uint32_t* Ahi = smu;
    uint32_t* Alo = Ahi + 128 * K1_APAD;
    uint32_t* Bhi = Alo + 128 * K1_APAD;
    uint32_t* Blo = Bhi + 64 * K1_BPAD;

    const int b = blockIdx.z, mt = blockIdx.y, n0 = blockIdx.x * 128;
    const int tid = threadIdx.x;

    for (int idx = tid; idx < 128 * 16; idx += 256) {
        int row = idx >> 4, c4 = (idx & 15) * 4;
        float4 w = *(const float4*)(Wq + (size_t)(mt * 128 + row) * CDIM + c4);
        float v[4] = {w.x, w.y, w.z, w.w};
#pragma unroll
        for (int j = 0; j < 4; j++) {
            uint32_t h = f2tf(v[j]);
            Ahi[row * K1_APAD + c4 + j] = h;
            Alo[row * K1_APAD + c4 + j] = f2tf(v[j] - __uint_as_float(h));
        }
    }
    for (int idx = tid; idx < 64 * 32; idx += 256) {
        int c = idx >> 5, n4 = (idx & 31) * 4;
        float4 w = *(const float4*)(x + (size_t)b * CDIM * NPOS + (size_t)c * NPOS + n0 + n4);
        float v[4] = {w.x, w.y, w.z, w.w};
#pragma unroll
        for (int j = 0; j < 4; j++) {
            uint32_t h = f2tf(v[j]);
            Bhi[c * K1_BPAD + n4 + j] = h;
            Blo[c * K1_BPAD + n4 + j] = f2tf(v[j] - __uint_as_float(h));
        }
    }
    __syncthreads();

    const int wid = tid >> 5, lane = tid & 31, g = lane >> 2, tig = lane & 3;
    const int wm = (wid >> 2) * 64, wn = (wid & 3) * 32;

    float c[4][4][4];
#pragma unroll
    for (int i = 0; i < 4; i++)
#pragma unroll
        for (int j = 0; j < 4; j++)
#pragma unroll
            for (int q = 0; q < 4; q++) c[i][j][q] = 0.f;

#pragma unroll
    for (int k8 = 0; k8 < 8; k8++) {
        const int kb = k8 * 8;
        uint32_t ah[4][4], al[4][4];
#pragma unroll
        for (int mf = 0; mf < 4; mf++) {
            int r0 = (wm + mf * 16 + g) * K1_APAD + kb + tig;
            int r1 = r0 + 8 * K1_APAD;
            ah[mf][0] = Ahi[r0]; ah[mf][1] = Ahi[r1];
            ah[mf][2] = Ahi[r0 + 4]; ah[mf][3] = Ahi[r1 + 4];
            al[mf][0] = Alo[r0]; al[mf][1] = Alo[r1];
            al[mf][2] = Alo[r0 + 4]; al[mf][3] = Alo[r1 + 4];
        }
        uint32_t bh[4][2], bl[4][2];
#pragma unroll
        for (int nf = 0; nf < 4; nf++) {
            int c0 = (kb + tig) * K1_BPAD + wn + nf * 8 + g;
            bh[nf][0] = Bhi[c0]; bh[nf][1] = Bhi[c0 + 4 * K1_BPAD];
            bl[nf][0] = Blo[c0]; bl[nf][1] = Blo[c0 + 4 * K1_BPAD];
        }
#pragma unroll
        for (int mf = 0; mf < 4; mf++)
#pragma unroll
            for (int nf = 0; nf < 4; nf++) {
                MMA(c[mf][nf], ah[mf], bh[nf]);
                MMA(c[mf][nf], ah[mf], bl[nf]);
                MMA(c[mf][nf], al[mf], bh[nf]);
            }
    }

    float* op = g_qkv + ((size_t)b * O3 + mt * 128 + wm) * NPOS + n0 + wn;
#pragma unroll
    for (int mf = 0; mf < 4; mf++)
#pragma unroll
        for (int nf = 0; nf < 4; nf++) {
            int col = nf * 8 + tig * 2;
            *(float2*)(op + (size_t)(mf * 16 + g) * NPOS + col) =
                make_float2(c[mf][nf][0], c[mf][nf][1]);
            *(float2*)(op + (size_t)(mf * 16 + g + 8) * NPOS + col) =
                make_float2(c[mf][nf][2], c[mf][nf][3]);
        }
}

// ---------------------------------------------------------------------------
// ATT2: partial (unnormalized) A over 128 positions. grid (9, 32, 8), 128 thr.
// Eq = exp(q) directly (softmax shift-invariance; |q| small, no overflow).
// ---------------------------------------------------------------------------
#define A2_PAD 132
#define A2_ARR (DHEAD * A2_PAD)
#define A2_SMEM (4 * A2_ARR * 4)

__global__ __launch_bounds__(128, 3) void att_a_kernel() {
    extern __shared__ uint32_t sm2[];
    uint32_t* Eqh = sm2;
    uint32_t* Eql = Eqh + A2_ARR;
    uint32_t* Ksh = Eql + A2_ARR;
    uint32_t* Ksl = Ksh + A2_ARR;
    float* Apart = (float*)sm2;   // alias after mma: [4][32][33]

    const int ch = blockIdx.x, g = blockIdx.y, sub = blockIdx.z;
    const int gc = g * NCH + ch;
    const int b = g >> 2, head = g & 3;
    const int tid = threadIdx.x, lane = tid & 31, wrp = tid >> 5;
    const int j = tid;

    const float* qbase = g_qkv + ((size_t)(b * O3 + head * DHEAD)) * NPOS + ch * CHUNK + sub * 128;
    const float* kbase = qbase + (size_t)INNER * NPOS;

    // K column softmax in registers
    float kr[DHEAD];
#pragma unroll
    for (int d = 0; d < DHEAD; d++) kr[d] = kbase[(size_t)d * NPOS + j];
    float km = -1e30f;
#pragma unroll
    for (int d = 0; d < DHEAD; d++) km = fmaxf(km, kr[d]);
    float ks = 0.f;
#pragma unroll
    for (int d = 0; d < DHEAD; d++) { kr[d] = __expf(kr[d] - km); ks += kr[d]; }
    float kinv = 1.0f / ks;
#pragma unroll
    for (int d = 0; d < DHEAD; d++) {
        float v = kr[d] * kinv;
        uint32_t h = f2tf(v);
        Ksh[d * A2_PAD + j] = h;
        Ksl[d * A2_PAD + j] = f2tf(v - __uint_as_float(h));
    }

    // Eq = exp(q), no max subtraction needed
    float qr[DHEAD];
#pragma unroll
    for (int d = 0; d < DHEAD; d++) qr[d] = qbase[(size_t)d * NPOS + j];
#pragma unroll
    for (int d = 0; d < DHEAD; d++) {
        float v = __expf(qr[d]);
        uint32_t h = f2tf(v);
        Eqh[d * A2_PAD + j] = h;
        Eql[d * A2_PAD + j] = f2tf(v - __uint_as_float(h));
    }
    __syncthreads();

    const int gq = lane >> 2, tig = lane & 3;
    float acc[2][4][4];
#pragma unroll
    for (int i = 0; i < 2; i++)
#pragma unroll
        for (int jj = 0; jj < 4; jj++)
#pragma unroll
            for (int q = 0; q < 4; q++) acc[i][jj][q] = 0.f;

#pragma unroll
    for (int kk = 0; kk < 4; kk++) {
        const int kb = (wrp * 4 + kk) * 8;
        uint32_t ah[2][4], al[2][4];
#pragma unroll
        for (int mf = 0; mf < 2; mf++) {
            int r0 = (mf * 16 + gq) * A2_PAD + kb + tig;
            int r1 = r0 + 8 * A2_PAD;
            ah[mf][0] = Eqh[r0]; ah[mf][1] = Eqh[r1];
            ah[mf][2] = Eqh[r0 + 4]; ah[mf][3] = Eqh[r1 + 4];
            al[mf][0] = Eql[r0]; al[mf][1] = Eql[r1];
            al[mf][2] = Eql[r0 + 4]; al[mf][3] = Eql[r1 + 4];
        }
        uint32_t bh[4][2], bl[4][2];
#pragma unroll
        for (int nf = 0; nf < 4; nf++) {
            int c0 = (nf * 8 + gq) * A2_PAD + kb + tig;
            bh[nf][0] = Ksh[c0]; bh[nf][1] = Ksh[c0 + 4];
            bl[nf][0] = Ksl[c0]; bl[nf][1] = Ksl[c0 + 4];
        }
#pragma unroll
        for (int mf = 0; mf < 2; mf++)
#pragma unroll
            for (int nf = 0; nf < 4; nf++) {
                MMA(acc[mf][nf], ah[mf], bh[nf]);
                MMA(acc[mf][nf], ah[mf], bl[nf]);
                MMA(acc[mf][nf], al[mf], bh[nf]);
            }
    }
    __syncthreads();

#pragma unroll
    for (int mf = 0; mf < 2; mf++)
#pragma unroll
        for (int nf = 0; nf < 4; nf++) {
            int row = mf * 16 + gq, col = nf * 8 + tig * 2;
            Apart[(wrp * 32 + row) * 33 + col]     = acc[mf][nf][0];
            Apart[(wrp * 32 + row) * 33 + col + 1] = acc[mf][nf][1];
            Apart[(wrp * 32 + row + 8) * 33 + col]     = acc[mf][nf][2];
            Apart[(wrp * 32 + row + 8) * 33 + col + 1] = acc[mf][nf][3];
        }
    __syncthreads();

    float* out = g_Apart[gc][sub];
#pragma unroll
    for (int r = 0; r < 8; r++) {
        int idx = tid + 128 * r;
        int d = idx >> 5, dp = idx & 31;
        float s = 0.f;
#pragma unroll
        for (int w = 0; w < 4; w++) s += Apart[(w * 32 + d) * 33 + dp];
        out[idx] = s;
    }
}

// ---------------------------------------------------------------------------
// WEFF: per (ch, b, head): reduce A partials, recover 1/Zq from A row sums
// (each Ks column sums to 1), scale, multiply into W_out block, emit hi/lo.
// grid (9, 8, 4), 256 threads.
// ---------------------------------------------------------------------------
__global__ __launch_bounds__(256, 6) void weff_kernel(const float* __restrict__ Wout) {
    __shared__ float A_s[DHEAD][DHEAD + 1];
    __shared__ float W_s[CDIM][DHEAD + 1];
    __shared__ float rinv[DHEAD];
    const int ch = blockIdx.x, b = blockIdx.y, head = blockIdx.z;
    const int cc = b * NCH + ch;
    const int gc = (b * HEADS + head) * NCH + ch;
    const int tid = threadIdx.x;

    // reduce A partials over 8 sub-blocks
#pragma unroll
    for (int r = 0; r < 4; r++) {
        int idx = tid + 256 * r;
        const float* ap = g_Apart[gc][0] + idx;
        float s = 0.f;
#pragma unroll
        for (int sub = 0; sub < 8; sub++) s += ap[sub * DHEAD * DHEAD];
        A_s[idx >> 5][idx & 31] = s;
    }
    // W_out block [64][32] for this head
#pragma unroll
    for (int r = 0; r < 8; r++) {
        int idx = tid + 256 * r;
        int o = idx >> 5, d = idx & 31;
        W_s[o][d] = Wout[(size_t)o * INNER + head * DHEAD + d];
    }
    __syncthreads();

    // Zq[d] = sum_dp A[d][dp]  (Ks columns each sum to 1)
    if (tid < DHEAD) {
        float s = 0.f;
#pragma unroll
        for (int dp = 0; dp < DHEAD; dp++) s += A_s[tid][dp];
        rinv[tid] = 1.0f / s;
    }
    __syncthreads();
    // scale A rows
#pragma unroll
    for (int r = 0; r < 4; r++) {
        int idx = tid + 256 * r;
        A_s[idx >> 5][idx & 31] *= rinv[idx >> 5];
    }
    __syncthreads();

    // W_eff[o][head*32+dp] = sum_d W_s[o][d] * A_s[d][dp]
#pragma unroll
    for (int r = 0; r < 8; r++) {
        int idx = tid + 256 * r;
        int o = idx >> 5, dp = idx & 31;
        float acc = 0.f;
#pragma unroll
        for (int d = 0; d < DHEAD; d++) acc += W_s[o][d] * A_s[d][dp];
        uint32_t h = f2tf(acc);
        g_Weff[cc][0][o][head * DHEAD + dp] = __uint_as_float(h);
        g_Weff[cc][1][o][head * DHEAD + dp] = __uint_as_float(f2tf(acc - __uint_as_float(h)));
    }
}

// ---------------------------------------------------------------------------
// K3' (fused): y = W_eff(b,ch) @ V + b_out, with groupnorm partials (unchanged)
// ---------------------------------------------------------------------------
#define K3_PAD 132
#define K3_SMEM ((64 * K3_PAD * 2 + 128 * K3_PAD * 2) * 4)

__global__ __launch_bounds__(256, 1) void outproj_mma_kernel(const float* __restrict__ bout,
                                                             float* __restrict__ y) {
    extern __shared__ uint32_t smu[];
    uint32_t* Ahi = smu;
    uint32_t* Alo = Ahi + 64 * K3_PAD;
    uint32_t* Bhi = Alo + 64 * K3_PAD;
    uint32_t* Blo = Bhi + 128 * K3_PAD;
    __shared__ float swp[8][8][2];

    const int b = blockIdx.y, n0 = blockIdx.x * 128, tid = threadIdx.x;
    const int cc = b * NCH + (n0 / CHUNK);

    for (int idx = tid; idx < 64 * 32; idx += 256) {
        int row = idx >> 5, c4 = (idx & 31) * 4;
        float4 h = *(const float4*)(&g_Weff[cc][0][row][c4]);
        float4 l = *(const float4*)(&g_Weff[cc][1][row][c4]);
        Ahi[row * K3_PAD + c4]     = __float_as_uint(h.x);
        Ahi[row * K3_PAD + c4 + 1] = __float_as_uint(h.y);
        Ahi[row * K3_PAD + c4 + 2] = __float_as_uint(h.z);
        Ahi[row * K3_PAD + c4 + 3] = __float_as_uint(h.w);
        Alo[row * K3_PAD + c4]     = __float_as_uint(l.x);
        Alo[row * K3_PAD + c4 + 1] = __float_as_uint(l.y);
        Alo[row * K3_PAD + c4 + 2] = __float_as_uint(l.z);
        Alo[row * K3_PAD + c4 + 3] = __float_as_uint(l.w);
    }
    const float* vbase = g_qkv + ((size_t)b * O3 + 2 * INNER) * NPOS + n0;
    for (int idx = tid; idx < 128 * 32; idx += 256) {
        int ic = idx >> 5, n4 = (idx & 31) * 4;
        float4 w = *(const float4*)(vbase + (size_t)ic * NPOS + n4);
        float v[4] = {w.x, w.y, w.z, w.w};
#pragma unroll
        for (int j = 0; j < 4; j++) {
            uint32_t h = f2tf(v[j]);
            Bhi[ic * K3_PAD + n4 + j] = h;
            Blo[ic * K3_PAD + n4 + j] = f2tf(v[j] - __uint_as_float(h));
        }
    }
    __syncthreads();

    const int wid = tid >> 5, lane = tid & 31, g = lane >> 2, tig = lane & 3;
    const int wn = wid * 16;

    float acc[4][2][4];
#pragma unroll
    for (int i = 0; i < 4; i++)
#pragma unroll
        for (int j = 0; j < 2; j++)
#pragma unroll
            for (int q = 0; q < 4; q++) acc[i][j][q] = 0.f;

#pragma unroll
    for (int k8 = 0; k8 < 16; k8++) {
        const int kb = k8 * 8;
        uint32_t ah[4][4], al[4][4];
#pragma unroll
        for (int mf = 0; mf < 4; mf++) {
            int r0 = (mf * 16 + g) * K3_PAD + kb + tig;
            int r1 = r0 + 8 * K3_PAD;
            ah[mf][0] = Ahi[r0]; ah[mf][1] = Ahi[r1];
            ah[mf][2] = Ahi[r0 + 4]; ah[mf][3] = Ahi[r1 + 4];
            al[mf][0] = Alo[r0]; al[mf][1] = Alo[r1];
            al[mf][2] = Alo[r0 + 4]; al[mf][3] = Alo[r1 + 4];
        }
        uint32_t bh[2][2], bl[2][2];
#pragma unroll
        for (int nf = 0; nf < 2; nf++) {
            int c0 = (kb + tig) * K3_PAD + wn + nf * 8 + g;
            bh[nf][0] = Bhi[c0]; bh[nf][1] = Bhi[c0 + 4 * K3_PAD];
            bl[nf][0] = Blo[c0]; bl[nf][1] = Blo[c0 + 4 * K3_PAD];
        }
#pragma unroll
        for (int mf = 0; mf < 4; mf++)
#pragma unroll
            for (int nf = 0; nf < 2; nf++) {
                MMA(acc[mf][nf], ah[mf], bh[nf]);
                MMA(acc[mf][nf], ah[mf], bl[nf]);
                MMA(acc[mf][nf], al[mf], bh[nf]);
            }
    }

    float gs[8], gq[8];
#pragma unroll
    for (int i = 0; i < 8; i++) { gs[i] = 0.f; gq[i] = 0.f; }

    float* yp = y + (size_t)b * CDIM * NPOS + n0 + wn;
#pragma unroll
    for (int mf = 0; mf < 4; mf++) {
        float bias0 = __ldg(bout + mf * 16 + g);
        float bias1 = __ldg(bout + mf * 16 + g + 8);
#pragma unroll
        for (int nf = 0; nf < 2; nf++) {
            int col = nf * 8 + tig * 2;
            float v0 = acc[mf][nf][0] + bias0, v1 = acc[mf][nf][1] + bias0;
            float v2 = acc[mf][nf][2] + bias1, v3 = acc[mf][nf][3] + bias1;
            *(float2*)(yp + (size_t)(mf * 16 + g) * NPOS + col) = make_float2(v0, v1);
            *(float2*)(yp + (size_t)(mf * 16 + g + 8) * NPOS + col) = make_float2(v2, v3);
            gs[2 * mf]     += v0 + v1;
            gq[2 * mf]     += v0 * v0 + v1 * v1;
            gs[2 * mf + 1] += v2 + v3;
            gq[2 * mf + 1] += v2 * v2 + v3 * v3;
        }
    }

#pragma unroll
    for (int gr = 0; gr < 8; gr++) {
        float s = gs[gr], q = gq[gr];
        for (int off = 16; off; off >>= 1) {
            s += __shfl_xor_sync(0xffffffffu, s, off);
            q += __shfl_xor_sync(0xffffffffu, q, off);
        }
        if (lane == 0) { swp[wid][gr][0] = s; swp[wid][gr][1] = q; }
    }
    __syncthreads();
    if (tid < 16) {
        int gr = tid >> 1, qq = tid & 1;
        float s = 0.f;
#pragma unroll
        for (int w = 0; w < 8; w++) s += swp[w][gr][qq];
        g_part[b][gr][blockIdx.x][qq] = s;
    }
}

// ---------------------------------------------------------------------------
// K4: groupnorm finalize (unchanged)
// ---------------------------------------------------------------------------
__global__ void gnorm_kernel(float* __restrict__ y,
                             const float* __restrict__ gamma,
                             const float* __restrict__ beta) {
    __shared__ float tmp[8][2];
    __shared__ float mu[8], rs[8];
    const int b = blockIdx.y, n0 = blockIdx.x * 256, tid = threadIdx.x;

    if (tid < 16) {
        int g = tid >> 1, qq = tid & 1;
        float s = 0.f;
        for (int t = 0; t < GN_TILES; t++) s += g_part[b][g][t][qq];
        tmp[g][qq] = s;
    }
    __syncthreads();
    if (tid < 8) {
        const float invn = 1.0f / (8.0f * NPOS);
        float m = tmp[tid][0] * invn;
        float v = tmp[tid][1] * invn - m * m;
        mu[tid] = m;
        rs[tid] = rsqrtf(v + 1e-5f);
    }
    __syncthreads();

    float* yb = y + (size_t)b * CDIM * NPOS + n0 + tid;
    for (int c = 0; c < CDIM; c++) {
        float val = yb[(size_t)c * NPOS];
        int g = c >> 3;
        yb[(size_t)c * NPOS] = (val - mu[g]) * rs[g] * __ldg(gamma + c) + __ldg(beta + c);
    }
}

// ---------------------------------------------------------------------------
extern "C" void kernel_launch(void* const* d_in, const int* in_sizes, int n_in,
                              void* d_out, int out_size) {
    const float* x     = (const float*)d_in[0];
    const float* Wqkv  = (const float*)d_in[1];
    const float* Wout  = (const float*)d_in[2];
    const float* bout  = (const float*)d_in[3];
    const float* gamma = (const float*)d_in[4];
    const float* beta  = (const float*)d_in[5];
    float* y = (float*)d_out;

    cudaFuncSetAttribute(qkv_mma_kernel, cudaFuncAttributeMaxDynamicSharedMemorySize, K1_SMEM);
    cudaFuncSetAttribute(att_a_kernel, cudaFuncAttributeMaxDynamicSharedMemorySize, A2_SMEM);
    cudaFuncSetAttribute(outproj_mma_kernel, cudaFuncAttributeMaxDynamicSharedMemorySize, K3_SMEM);

    qkv_mma_kernel<<<dim3(72, 3, B_), 256, K1_SMEM>>>(x, Wqkv);
    att_a_kernel<<<dim3(NCH, 32, 8), 128, A2_SMEM>>>();
    weff_kernel<<<dim3(NCH, B_, HEADS), 256>>>(Wout);
    outproj_mma_kernel<<<dim3(GN_TILES, B_), 256, K3_SMEM>>>(bout, y);
    gnorm_kernel<<<dim3(K4_TILES, B_), 256>>>(y, gamma, beta);
}

// round 6
// speedup vs baseline: 1.8083x; 1.6184x over previous
#include <cuda_runtime.h>
#include <cstdint>

// Problem constants
#define B_     8
#define CDIM   64
#define NPOS   9216      // 96*96
#define INNER  128
#define O3     384       // 3*INNER
#define HEADS  4
#define DHEAD  32
#define NCH    9
#define CHUNK  1024
#define NGC    (32 * NCH)   // 288 (g, ch) pairs
#define GN_TILES 72

// Scratch (device globals — no allocations allowed)
__device__ __align__(16) float g_qkv[(size_t)B_ * O3 * NPOS];      // [b][o][n]
__device__ float g_part[B_][8][GN_TILES][2];                        // groupnorm partials
__device__ __align__(16) float g_Apart[NGC][8][DHEAD * DHEAD];      // partial A (unnormalized)
__device__ __align__(16) float g_Weff[B_ * NCH][2][CDIM][INNER];    // fused weights hi/lo

// ---------------------------------------------------------------------------
__device__ __forceinline__ uint32_t f2tf(float x) {
    uint32_t r;
    asm("cvt.rna.tf32.f32 %0, %1;" : "=r"(r) : "f"(x));
    return r;
}

#define MMA(d, a, b)                                                          \
    asm volatile(                                                             \
        "mma.sync.aligned.m16n8k8.row.col.f32.tf32.tf32.f32 "                 \
        "{%0,%1,%2,%3},{%4,%5,%6,%7},{%8,%9},{%0,%1,%2,%3};"                  \
        : "+f"((d)[0]), "+f"((d)[1]), "+f"((d)[2]), "+f"((d)[3])              \
        : "r"((a)[0]), "r"((a)[1]), "r"((a)[2]), "r"((a)[3]),                 \
          "r"((b)[0]), "r"((b)[1]))

// ---------------------------------------------------------------------------
// K1 (mma): qkv[b][o][n] = sum_c W_qkv[o][c] * x[b][c][n]
// A (W tile, hi/lo) in smem; B (x) streamed from global, split on the fly.
// CTA tile [128 M x 128 N], K=64. grid (72, 3, 8), 256 threads, occ 2.
// ---------------------------------------------------------------------------
#define K1_APAD 68
#define K1_SMEM (128 * K1_APAD * 2 * 4)

__global__ __launch_bounds__(256, 2) void qkv_mma_kernel(const float* __restrict__ x,
                                                         const float* __restrict__ Wq) {
    extern __shared__ uint32_t smu[];
    uint32_t* Ahi = smu;
    uint32_t* Alo = Ahi + 128 * K1_APAD;

    const int b = blockIdx.z, mt = blockIdx.y, n0 = blockIdx.x * 128;
    const int tid = threadIdx.x;

    // load + split W tile [128 M x 64 K]
    for (int idx = tid; idx < 128 * 16; idx += 256) {
        int row = idx >> 4, c4 = (idx & 15) * 4;
        float4 w = *(const float4*)(Wq + (size_t)(mt * 128 + row) * CDIM + c4);
        float v[4] = {w.x, w.y, w.z, w.w};
#pragma unroll
        for (int j = 0; j < 4; j++) {
            uint32_t h = f2tf(v[j]);
            Ahi[row * K1_APAD + c4 + j] = h;
            Alo[row * K1_APAD + c4 + j] = f2tf(v[j] - __uint_as_float(h));
        }
    }
    __syncthreads();

    const int wid = tid >> 5, lane = tid & 31, g = lane >> 2, tig = lane & 3;
    const int wm = (wid >> 2) * 64, wn = (wid & 3) * 32;

    const float* xb = x + (size_t)b * CDIM * NPOS + n0;

    float c[4][4][4];
#pragma unroll
    for (int i = 0; i < 4; i++)
#pragma unroll
        for (int j = 0; j < 4; j++)
#pragma unroll
            for (int q = 0; q < 4; q++) c[i][j][q] = 0.f;

#pragma unroll
    for (int k8 = 0; k8 < 8; k8++) {
        const int kb = k8 * 8;
        // B fragments streamed from global (rows kb+tig, kb+tig+4)
        const float* xr0 = xb + (size_t)(kb + tig) * NPOS;
        const float* xr1 = xr0 + 4 * NPOS;
        uint32_t bh[4][2], bl[4][2];
#pragma unroll
        for (int nf = 0; nf < 4; nf++) {
            int col = wn + nf * 8 + g;
            float v0 = __ldg(xr0 + col);
            float v1 = __ldg(xr1 + col);
            uint32_t h0 = f2tf(v0), h1 = f2tf(v1);
            bh[nf][0] = h0; bh[nf][1] = h1;
            bl[nf][0] = f2tf(v0 - __uint_as_float(h0));
            bl[nf][1] = f2tf(v1 - __uint_as_float(h1));
        }
        uint32_t ah[4][4], al[4][4];
#pragma unroll
        for (int mf = 0; mf < 4; mf++) {
            int r0 = (wm + mf * 16 + g) * K1_APAD + kb + tig;
            int r1 = r0 + 8 * K1_APAD;
            ah[mf][0] = Ahi[r0]; ah[mf][1] = Ahi[r1];
            ah[mf][2] = Ahi[r0 + 4]; ah[mf][3] = Ahi[r1 + 4];
            al[mf][0] = Alo[r0]; al[mf][1] = Alo[r1];
            al[mf][2] = Alo[r0 + 4]; al[mf][3] = Alo[r1 + 4];
        }
#pragma unroll
        for (int mf = 0; mf < 4; mf++)
#pragma unroll
            for (int nf = 0; nf < 4; nf++) {
                MMA(c[mf][nf], ah[mf], bh[nf]);
                MMA(c[mf][nf], ah[mf], bl[nf]);
                MMA(c[mf][nf], al[mf], bh[nf]);
            }
    }

    float* op = g_qkv + ((size_t)b * O3 + mt * 128 + wm) * NPOS + n0 + wn;
#pragma unroll
    for (int mf = 0; mf < 4; mf++)
#pragma unroll
        for (int nf = 0; nf < 4; nf++) {
            int col = nf * 8 + tig * 2;
            *(float2*)(op + (size_t)(mf * 16 + g) * NPOS + col) =
                make_float2(c[mf][nf][0], c[mf][nf][1]);
            *(float2*)(op + (size_t)(mf * 16 + g + 8) * NPOS + col) =
                make_float2(c[mf][nf][2], c[mf][nf][3]);
        }
}

// ---------------------------------------------------------------------------
// ATT2: partial (unnormalized) A over 128 positions. grid (9, 32, 8), 128 thr.
// (unchanged)
// ---------------------------------------------------------------------------
#define A2_PAD 132
#define A2_ARR (DHEAD * A2_PAD)
#define A2_SMEM (4 * A2_ARR * 4)

__global__ __launch_bounds__(128, 3) void att_a_kernel() {
    extern __shared__ uint32_t sm2[];
    uint32_t* Eqh = sm2;
    uint32_t* Eql = Eqh + A2_ARR;
    uint32_t* Ksh = Eql + A2_ARR;
    uint32_t* Ksl = Ksh + A2_ARR;
    float* Apart = (float*)sm2;   // alias after mma: [4][32][33]

    const int ch = blockIdx.x, g = blockIdx.y, sub = blockIdx.z;
    const int gc = g * NCH + ch;
    const int b = g >> 2, head = g & 3;
    const int tid = threadIdx.x, lane = tid & 31, wrp = tid >> 5;
    const int j = tid;

    const float* qbase = g_qkv + ((size_t)(b * O3 + head * DHEAD)) * NPOS + ch * CHUNK + sub * 128;
    const float* kbase = qbase + (size_t)INNER * NPOS;

    float kr[DHEAD];
#pragma unroll
    for (int d = 0; d < DHEAD; d++) kr[d] = kbase[(size_t)d * NPOS + j];
    float km = -1e30f;
#pragma unroll
    for (int d = 0; d < DHEAD; d++) km = fmaxf(km, kr[d]);
    float ks = 0.f;
#pragma unroll
    for (int d = 0; d < DHEAD; d++) { kr[d] = __expf(kr[d] - km); ks += kr[d]; }
    float kinv = 1.0f / ks;
#pragma unroll
    for (int d = 0; d < DHEAD; d++) {
        float v = kr[d] * kinv;
        uint32_t h = f2tf(v);
        Ksh[d * A2_PAD + j] = h;
        Ksl[d * A2_PAD + j] = f2tf(v - __uint_as_float(h));
    }

    float qr[DHEAD];
#pragma unroll
    for (int d = 0; d < DHEAD; d++) qr[d] = qbase[(size_t)d * NPOS + j];
#pragma unroll
    for (int d = 0; d < DHEAD; d++) {
        float v = __expf(qr[d]);
        uint32_t h = f2tf(v);
        Eqh[d * A2_PAD + j] = h;
        Eql[d * A2_PAD + j] = f2tf(v - __uint_as_float(h));
    }
    __syncthreads();

    const int gq = lane >> 2, tig = lane & 3;
    float acc[2][4][4];
#pragma unroll
    for (int i = 0; i < 2; i++)
#pragma unroll
        for (int jj = 0; jj < 4; jj++)
#pragma unroll
            for (int q = 0; q < 4; q++) acc[i][jj][q] = 0.f;

#pragma unroll
    for (int kk = 0; kk < 4; kk++) {
        const int kb = (wrp * 4 + kk) * 8;
        uint32_t ah[2][4], al[2][4];
#pragma unroll
        for (int mf = 0; mf < 2; mf++) {
            int r0 = (mf * 16 + gq) * A2_PAD + kb + tig;
            int r1 = r0 + 8 * A2_PAD;
            ah[mf][0] = Eqh[r0]; ah[mf][1] = Eqh[r1];
            ah[mf][2] = Eqh[r0 + 4]; ah[mf][3] = Eqh[r1 + 4];
            al[mf][0] = Eql[r0]; al[mf][1] = Eql[r1];
            al[mf][2] = Eql[r0 + 4]; al[mf][3] = Eql[r1 + 4];
        }
        uint32_t bh[4][2], bl[4][2];
#pragma unroll
        for (int nf = 0; nf < 4; nf++) {
            int c0 = (nf * 8 + gq) * A2_PAD + kb + tig;
            bh[nf][0] = Ksh[c0]; bh[nf][1] = Ksh[c0 + 4];
            bl[nf][0] = Ksl[c0]; bl[nf][1] = Ksl[c0 + 4];
        }
#pragma unroll
        for (int mf = 0; mf < 2; mf++)
#pragma unroll
            for (int nf = 0; nf < 4; nf++) {
                MMA(acc[mf][nf], ah[mf], bh[nf]);
                MMA(acc[mf][nf], ah[mf], bl[nf]);
                MMA(acc[mf][nf], al[mf], bh[nf]);
            }
    }
    __syncthreads();

#pragma unroll
    for (int mf = 0; mf < 2; mf++)
#pragma unroll
        for (int nf = 0; nf < 4; nf++) {
            int row = mf * 16 + gq, col = nf * 8 + tig * 2;
            Apart[(wrp * 32 + row) * 33 + col]     = acc[mf][nf][0];
            Apart[(wrp * 32 + row) * 33 + col + 1] = acc[mf][nf][1];
            Apart[(wrp * 32 + row + 8) * 33 + col]     = acc[mf][nf][2];
            Apart[(wrp * 32 + row + 8) * 33 + col + 1] = acc[mf][nf][3];
        }
    __syncthreads();

    float* out = g_Apart[gc][sub];
#pragma unroll
    for (int r = 0; r < 8; r++) {
        int idx = tid + 128 * r;
        int d = idx >> 5, dp = idx & 31;
        float s = 0.f;
#pragma unroll
        for (int w = 0; w < 4; w++) s += Apart[(w * 32 + d) * 33 + dp];
        out[idx] = s;
    }
}

// ---------------------------------------------------------------------------
// WEFF: grid (9, 8, 4), 256 threads (unchanged)
// ---------------------------------------------------------------------------
__global__ __launch_bounds__(256, 6) void weff_kernel(const float* __restrict__ Wout) {
    __shared__ float A_s[DHEAD][DHEAD + 1];
    __shared__ float W_s[CDIM][DHEAD + 1];
    __shared__ float rinv[DHEAD];
    const int ch = blockIdx.x, b = blockIdx.y, head = blockIdx.z;
    const int cc = b * NCH + ch;
    const int gc = (b * HEADS + head) * NCH + ch;
    const int tid = threadIdx.x;

#pragma unroll
    for (int r = 0; r < 4; r++) {
        int idx = tid + 256 * r;
        const float* ap = g_Apart[gc][0] + idx;
        float s = 0.f;
#pragma unroll
        for (int sub = 0; sub < 8; sub++) s += ap[sub * DHEAD * DHEAD];
        A_s[idx >> 5][idx & 31] = s;
    }
#pragma unroll
    for (int r = 0; r < 8; r++) {
        int idx = tid + 256 * r;
        int o = idx >> 5, d = idx & 31;
        W_s[o][d] = Wout[(size_t)o * INNER + head * DHEAD + d];
    }
    __syncthreads();

    if (tid < DHEAD) {
        float s = 0.f;
#pragma unroll
        for (int dp = 0; dp < DHEAD; dp++) s += A_s[tid][dp];
        rinv[tid] = 1.0f / s;
    }
    __syncthreads();
#pragma unroll
    for (int r = 0; r < 4; r++) {
        int idx = tid + 256 * r;
        A_s[idx >> 5][idx & 31] *= rinv[idx >> 5];
    }
    __syncthreads();

#pragma unroll
    for (int r = 0; r < 8; r++) {
        int idx = tid + 256 * r;
        int o = idx >> 5, dp = idx & 31;
        float acc = 0.f;
#pragma unroll
        for (int d = 0; d < DHEAD; d++) acc += W_s[o][d] * A_s[d][dp];
        uint32_t h = f2tf(acc);
        g_Weff[cc][0][o][head * DHEAD + dp] = __uint_as_float(h);
        g_Weff[cc][1][o][head * DHEAD + dp] = __uint_as_float(f2tf(acc - __uint_as_float(h)));
    }
}

// ---------------------------------------------------------------------------
// K3' (fused): y = W_eff(b,ch) @ V + b_out, groupnorm partials.
// A (W_eff hi/lo) in smem; B (V) streamed from global, split on the fly.
// CTA tile [64 M x 128 N], K=128. grid (72, 8), 256 threads, occ 2.
// ---------------------------------------------------------------------------
#define K3_PAD 132
#define K3_SMEM (64 * K3_PAD * 2 * 4)

__global__ __launch_bounds__(256, 2) void outproj_mma_kernel(const float* __restrict__ bout,
                                                             float* __restrict__ y) {
    extern __shared__ uint32_t smu[];
    uint32_t* Ahi = smu;
    uint32_t* Alo = Ahi + 64 * K3_PAD;
    __shared__ float swp[8][8][2];

    const int b = blockIdx.y, n0 = blockIdx.x * 128, tid = threadIdx.x;
    const int cc = b * NCH + (n0 / CHUNK);

    // A tile: pre-split W_eff
    for (int idx = tid; idx < 64 * 32; idx += 256) {
        int row = idx >> 5, c4 = (idx & 31) * 4;
        float4 h = *(const float4*)(&g_Weff[cc][0][row][c4]);
        float4 l = *(const float4*)(&g_Weff[cc][1][row][c4]);
        Ahi[row * K3_PAD + c4]     = __float_as_uint(h.x);
        Ahi[row * K3_PAD + c4 + 1] = __float_as_uint(h.y);
        Ahi[row * K3_PAD + c4 + 2] = __float_as_uint(h.z);
        Ahi[row * K3_PAD + c4 + 3] = __float_as_uint(h.w);
        Alo[row * K3_PAD + c4]     = __float_as_uint(l.x);
        Alo[row * K3_PAD + c4 + 1] = __float_as_uint(l.y);
        Alo[row * K3_PAD + c4 + 2] = __float_as_uint(l.z);
        Alo[row * K3_PAD + c4 + 3] = __float_as_uint(l.w);
    }
    __syncthreads();

    const int wid = tid >> 5, lane = tid & 31, g = lane >> 2, tig = lane & 3;
    const int wn = wid * 16;
    const float* vbase = g_qkv + ((size_t)b * O3 + 2 * INNER) * NPOS + n0;

    float acc[4][2][4];
#pragma unroll
    for (int i = 0; i < 4; i++)
#pragma unroll
        for (int j = 0; j < 2; j++)
#pragma unroll
            for (int q = 0; q < 4; q++) acc[i][j][q] = 0.f;

#pragma unroll
    for (int k8 = 0; k8 < 16; k8++) {
        const int kb = k8 * 8;
        const float* vr0 = vbase + (size_t)(kb + tig) * NPOS;
        const float* vr1 = vr0 + 4 * NPOS;
        uint32_t bh[2][2], bl[2][2];
#pragma unroll
        for (int nf = 0; nf < 2; nf++) {
            int col = wn + nf * 8 + g;
            float v0 = __ldg(vr0 + col);
            float v1 = __ldg(vr1 + col);
            uint32_t h0 = f2tf(v0), h1 = f2tf(v1);
            bh[nf][0] = h0; bh[nf][1] = h1;
            bl[nf][0] = f2tf(v0 - __uint_as_float(h0));
            bl[nf][1] = f2tf(v1 - __uint_as_float(h1));
        }
        uint32_t ah[4][4], al[4][4];
#pragma unroll
        for (int mf = 0; mf < 4; mf++) {
            int r0 = (mf * 16 + g) * K3_PAD + kb + tig;
            int r1 = r0 + 8 * K3_PAD;
            ah[mf][0] = Ahi[r0]; ah[mf][1] = Ahi[r1];
            ah[mf][2] = Ahi[r0 + 4]; ah[mf][3] = Ahi[r1 + 4];
            al[mf][0] = Alo[r0]; al[mf][1] = Alo[r1];
            al[mf][2] = Alo[r0 + 4]; al[mf][3] = Alo[r1 + 4];
        }
#pragma unroll
        for (int mf = 0; mf < 4; mf++)
#pragma unroll
            for (int nf = 0; nf < 2; nf++) {
                MMA(acc[mf][nf], ah[mf], bh[nf]);
                MMA(acc[mf][nf], ah[mf], bl[nf]);
                MMA(acc[mf][nf], al[mf], bh[nf]);
            }
    }

    float gs[8], gq[8];
#pragma unroll
    for (int i = 0; i < 8; i++) { gs[i] = 0.f; gq[i] = 0.f; }

    float* yp = y + (size_t)b * CDIM * NPOS + n0 + wn;
#pragma unroll
    for (int mf = 0; mf < 4; mf++) {
        float bias0 = __ldg(bout + mf * 16 + g);
        float bias1 = __ldg(bout + mf * 16 + g + 8);
#pragma unroll
        for (int nf = 0; nf < 2; nf++) {
            int col = nf * 8 + tig * 2;
            float v0 = acc[mf][nf][0] + bias0, v1 = acc[mf][nf][1] + bias0;
            float v2 = acc[mf][nf][2] + bias1, v3 = acc[mf][nf][3] + bias1;
            *(float2*)(yp + (size_t)(mf * 16 + g) * NPOS + col) = make_float2(v0, v1);
            *(float2*)(yp + (size_t)(mf * 16 + g + 8) * NPOS + col) = make_float2(v2, v3);
            gs[2 * mf]     += v0 + v1;
            gq[2 * mf]     += v0 * v0 + v1 * v1;
            gs[2 * mf + 1] += v2 + v3;
            gq[2 * mf + 1] += v2 * v2 + v3 * v3;
        }
    }

#pragma unroll
    for (int gr = 0; gr < 8; gr++) {
        float s = gs[gr], q = gq[gr];
        for (int off = 16; off; off >>= 1) {
            s += __shfl_xor_sync(0xffffffffu, s, off);
            q += __shfl_xor_sync(0xffffffffu, q, off);
        }
        if (lane == 0) { swp[wid][gr][0] = s; swp[wid][gr][1] = q; }
    }
    __syncthreads();
    if (tid < 16) {
        int gr = tid >> 1, qq = tid & 1;
        float s = 0.f;
#pragma unroll
        for (int w = 0; w < 8; w++) s += swp[w][gr][qq];
        g_part[b][gr][blockIdx.x][qq] = s;
    }
}

// ---------------------------------------------------------------------------
// K4: groupnorm finalize, float4-vectorized. grid (9, 8), 256 threads.
// ---------------------------------------------------------------------------
__global__ __launch_bounds__(256, 4) void gnorm_kernel(float* __restrict__ y,
                                                       const float* __restrict__ gamma,
                                                       const float* __restrict__ beta) {
    __shared__ float tmp[8][2];
    __shared__ float mu[8], rs[8];
    const int b = blockIdx.y, n0 = blockIdx.x * 1024, tid = threadIdx.x;

    if (tid < 16) {
        int g = tid >> 1, qq = tid & 1;
        float s = 0.f;
        for (int t = 0; t < GN_TILES; t++) s += g_part[b][g][t][qq];
        tmp[g][qq] = s;
    }
    __syncthreads();
    if (tid < 8) {
        const float invn = 1.0f / (8.0f * NPOS);
        float m = tmp[tid][0] * invn;
        float v = tmp[tid][1] * invn - m * m;
        mu[tid] = m;
        rs[tid] = rsqrtf(v + 1e-5f);
    }
    __syncthreads();

    float* yb = y + (size_t)b * CDIM * NPOS + n0 + tid * 4;
#pragma unroll 4
    for (int c = 0; c < CDIM; c++) {
        float4* p = (float4*)(yb + (size_t)c * NPOS);
        float4 v = *p;
        int g = c >> 3;
        float sc = rs[g] * __ldg(gamma + c);
        float sh = __ldg(beta + c) - mu[g] * sc;
        v.x = v.x * sc + sh;
        v.y = v.y * sc + sh;
        v.z = v.z * sc + sh;
        v.w = v.w * sc + sh;
        *p = v;
    }
}

// ---------------------------------------------------------------------------
extern "C" void kernel_launch(void* const* d_in, const int* in_sizes, int n_in,
                              void* d_out, int out_size) {
    const float* x     = (const float*)d_in[0];
    const float* Wqkv  = (const float*)d_in[1];
    const float* Wout  = (const float*)d_in[2];
    const float* bout  = (const float*)d_in[3];
    const float* gamma = (const float*)d_in[4];
    const float* beta  = (const float*)d_in[5];
    float* y = (float*)d_out;

    cudaFuncSetAttribute(qkv_mma_kernel, cudaFuncAttributeMaxDynamicSharedMemorySize, K1_SMEM);
    cudaFuncSetAttribute(att_a_kernel, cudaFuncAttributeMaxDynamicSharedMemorySize, A2_SMEM);
    cudaFuncSetAttribute(outproj_mma_kernel, cudaFuncAttributeMaxDynamicSharedMemorySize, K3_SMEM);

    qkv_mma_kernel<<<dim3(72, 3, B_), 256, K1_SMEM>>>(x, Wqkv);
    att_a_kernel<<<dim3(NCH, 32, 8), 128, A2_SMEM>>>();
    weff_kernel<<<dim3(NCH, B_, HEADS), 256>>>(Wout);
    outproj_mma_kernel<<<dim3(GN_TILES, B_), 256, K3_SMEM>>>(bout, y);
    gnorm_kernel<<<dim3(NCH, B_), 256>>>(y, gamma, beta);
}